// round 5
// baseline (speedup 1.0000x reference)
#include <cuda_runtime.h>
#include <cuda_fp16.h>
#include <cstdint>

// VanillaRNN via warp-level HMMA, fp16 3-pass hi/lo split, fp32 accum.
// R5: 512 threads / 16 warps (4 per SMSP). Each warp owns 16 M-rows and keeps
// ALL its loop-invariant A_hi fragments in 64 registers; only A_lo and B
// stream through LDSM each step. Smem: W_lo 128K (staged as W_hi first),
// h double-buffer 32K, x ring.

#define BATCH 2048
#define SEQT  512
#define HDIM  256
#define NCOL  16
#define NBLK  128
#define NTHR  512
#define NSTEPS 510

// smem byte offsets
#define SM_WLO 0          // init: W_hi staging; steady: W_lo [256 rows][512B] swizzled
#define SM_B   131072     // h buffers: [buf0 hi 8K | lo 8K][buf1 hi 8K | lo 8K]
#define SM_XR  163840     // x ring: 2 slots x 16 f32
#define SM_TOTAL 163968

__device__ __forceinline__ uint32_t s2u(const void* p) {
    uint32_t a;
    asm("{ .reg .u64 t; cvta.to.shared.u64 t, %1; cvt.u32.u64 %0, t; }" : "=r"(a) : "l"(p));
    return a;
}

#define LDSM4(r, a)                                                               \
    asm volatile("ldmatrix.sync.aligned.m8n8.x4.shared.b16 {%0,%1,%2,%3}, [%4];"  \
                 : "=r"((r)[0]), "=r"((r)[1]), "=r"((r)[2]), "=r"((r)[3])         \
                 : "r"(a))

__device__ __forceinline__ void mma16816(float* d, const uint32_t* a,
                                         uint32_t b0, uint32_t b1) {
    asm volatile("mma.sync.aligned.m16n8k16.row.col.f32.f16.f16.f32 "
                 "{%0,%1,%2,%3}, {%4,%5,%6,%7}, {%8,%9}, {%0,%1,%2,%3};"
                 : "+f"(d[0]), "+f"(d[1]), "+f"(d[2]), "+f"(d[3])
                 : "r"(a[0]), "r"(a[1]), "r"(a[2]), "r"(a[3]), "r"(b0), "r"(b1));
}

__device__ __forceinline__ float tanh_fast(float v) {
    float e = __expf(2.0f * v);
    return 1.0f - __fdividef(2.0f, e + 1.0f);
}

__global__ void __launch_bounds__(NTHR, 1) VanillaRNN_54984171323420_kernel(
    const float* __restrict__ x,    // [2048, 512]
    const float* __restrict__ Whx,  // [256, 1]
    const float* __restrict__ Whh,  // [256, 256]
    const float* __restrict__ Wph,  // [10, 256]
    const float* __restrict__ bh,   // [256, 2048]
    const float* __restrict__ bp,   // [10, 2048]
    float* __restrict__ out)        // [2048, 10]
{
    extern __shared__ char smc[];
    const uint32_t sb = s2u(smc);
    const int tid = threadIdx.x;
    const int w = tid >> 5;          // warp 0..15 -> m rows [16w, 16w+16)
    const int l = tid & 31;
    const int lq = l >> 2;
    const int lr = (l & 3) * 2;
    const int lx = l >> 4;
    const int l7 = l & 7;
    const int m0 = 16 * w;
    const int j0 = blockIdx.x * NCOL;

    // ---------------- stage W_hi into smem (swizzled, 512B rows) ----------------
    for (int idx = tid; idx < HDIM * HDIM; idx += NTHR) {
        int m = idx >> 8, k = idx & 255;
        __half hi = __float2half_rn(Whh[idx]);
        uint32_t ch = (uint32_t)(((k >> 3) ^ (m & 7)) << 4);
        *(__half*)(smc + SM_WLO + m * 512 + ch + (k & 7) * 2) = hi;
    }
    // x: slot1 <- x_0 ; preload x_1 into reg
    float xn1 = 0.0f;
    if (tid < NCOL) {
        const float* xr = x + (j0 + tid) * SEQT;
        *(float*)(smc + SM_XR + 64 + tid * 4) = xr[0];
        xn1 = xr[1];
    }
    __syncthreads();

    // ---------------- A_hi fragments -> registers (loop-invariant) ----------------
    const uint32_t rowAL = sb + SM_WLO + (uint32_t)(m0 + (l & 15)) * 512;
    uint32_t ahi[16][4];
#pragma unroll
    for (int ks = 0; ks < 16; ks++)
        LDSM4(ahi[ks], rowAL + (uint32_t)(((2 * ks + lx) ^ l7) << 4));
    __syncthreads();

    // ---------------- overwrite staging with W_lo (residual) ----------------
    for (int idx = tid; idx < HDIM * HDIM; idx += NTHR) {
        int m = idx >> 8, k = idx & 255;
        float wv = Whh[idx];
        __half hi = __float2half_rn(wv);
        __half lo = __float2half_rn(wv - __half2float(hi));
        uint32_t ch = (uint32_t)(((k >> 3) ^ (m & 7)) << 4);
        *(__half*)(smc + SM_WLO + m * 512 + ch + (k & 7) * 2) = lo;
    }

    // ---------------- bias / Whx fragments (8 D elems per thread) ----------------
    float bias[8];
    float wx[2];
    wx[0] = Whx[m0 + lq];
    wx[1] = Whx[m0 + lq + 8];
#pragma unroll
    for (int tn = 0; tn < 2; tn++)
#pragma unroll
        for (int e = 0; e < 4; e++) {
            int m = m0 + lq + ((e >> 1) ? 8 : 0);
            int n = 8 * tn + lr + (e & 1);
            bias[tn * 4 + e] = bh[m * BATCH + j0 + n];
        }

    // ---------------- prologue: h1 = tanh(b_h + Whx*x_0) -> buf0 ----------------
#pragma unroll
    for (int tn = 0; tn < 2; tn++)
#pragma unroll
        for (int e = 0; e < 4; e++) {
            int n = 8 * tn + lr + (e & 1);
            int mh = e >> 1;
            int m = m0 + lq + (mh ? 8 : 0);
            float xv = *(const float*)(smc + SM_XR + 64 + n * 4);
            float h = tanh_fast(bias[tn * 4 + e] + wx[mh] * xv);
            __half hi = __float2half_rn(h);
            __half lo = __float2half_rn(h - __half2float(hi));
            uint32_t off = (uint32_t)n * 512 + ((((uint32_t)m >> 3) ^ (n & 7)) << 4) + (m & 7) * 2;
            *(__half*)(smc + SM_B + off) = hi;
            *(__half*)(smc + SM_B + 8192 + off) = lo;
        }
    if (tid < NCOL) *(float*)(smc + SM_XR + tid * 4) = xn1;  // slot0 <- x_1
    __syncthreads();

    const uint32_t rowBb = sb + SM_B + (uint32_t)(l & 15) * 512;

    // ================= recurrence: 510 HMMA steps, 1 bar/step =================
#pragma unroll 2
    for (int it = 0; it < NSTEPS; it++) {
        const int p = it & 1;                 // read buf p, write buf 1-p
        float xnext = 0.0f;
        if (tid < NCOL) xnext = x[(j0 + tid) * SEQT + it + 2];

        const uint32_t rowB = rowBb + (uint32_t)p * 16384;

        float d[8];
#pragma unroll
        for (int q = 0; q < 8; q++) d[q] = bias[q];

#pragma unroll
        for (int ks = 0; ks < 16; ks++) {
            const uint32_t ch = (uint32_t)(((2 * ks + lx) ^ l7) << 4);
            uint32_t bh4[4], bl4[4], al[4];
            LDSM4(bh4, rowB + ch);
            LDSM4(bl4, rowB + 8192 + ch);
            LDSM4(al, rowAL + ch);
            // pass 1: W_hi . h_hi ; pass 2: W_lo . h_hi ; pass 3: W_hi . h_lo
            mma16816(&d[0], ahi[ks], bh4[0], bh4[2]);
            mma16816(&d[4], ahi[ks], bh4[1], bh4[3]);
            mma16816(&d[0], al,      bh4[0], bh4[2]);
            mma16816(&d[4], al,      bh4[1], bh4[3]);
            mma16816(&d[0], ahi[ks], bl4[0], bl4[2]);
            mma16816(&d[4], ahi[ks], bl4[1], bl4[3]);
        }

        // ---- epilogue: h_{it+2} = tanh(D + Whx*x_{it+1}) -> buf 1-p ----
        const uint32_t xsl = (uint32_t)(SM_XR + p * 64);
        const uint32_t bufw = (uint32_t)(SM_B + (1 - p) * 16384);
#pragma unroll
        for (int tn = 0; tn < 2; tn++)
#pragma unroll
            for (int e = 0; e < 4; e++) {
                int n = 8 * tn + lr + (e & 1);
                int mh = e >> 1;
                int m = m0 + lq + (mh ? 8 : 0);
                float xv = *(const float*)(smc + xsl + n * 4);
                float pre = fmaf(wx[mh], xv, d[tn * 4 + e]);
                float h = tanh_fast(pre);
                __half hi = __float2half_rn(h);
                __half lo = __float2half_rn(h - __half2float(hi));
                uint32_t off = (uint32_t)n * 512 + ((((uint32_t)m >> 3) ^ (n & 7)) << 4) + (m & 7) * 2;
                *(__half*)(smc + bufw + off) = hi;
                *(__half*)(smc + bufw + 8192 + off) = lo;
            }
        if (tid < NCOL) *(float*)(smc + SM_XR + (1 - p) * 64 + tid * 4) = xnext;
        __syncthreads();
    }

    // ================= projection: out = Wph @ h + bp =================
    // final h (after 511 updates) lives in buf0 (it=509 wrote buf 1-p = 0)
    if (tid < 10 * NCOL) {
        const int c = tid >> 4, j = tid & 15;
        float s = bp[c * BATCH + j0 + j];
        const float* wr = Wph + c * HDIM;
#pragma unroll 8
        for (int k = 0; k < HDIM; k++) {
            uint32_t off = (uint32_t)j * 512 + ((((uint32_t)k >> 3) ^ (j & 7)) << 4) + (k & 7) * 2;
            float hv = __half2float(*(__half*)(smc + SM_B + off)) +
                       __half2float(*(__half*)(smc + SM_B + 8192 + off));
            s = fmaf(wr[k], hv, s);
        }
        out[(j0 + j) * 10 + c] = s;
    }
}

extern "C" void kernel_launch(void* const* d_in, const int* in_sizes, int n_in,
                              void* d_out, int out_size) {
    const float* x   = (const float*)d_in[0];
    const float* Whx = (const float*)d_in[1];
    const float* Whh = (const float*)d_in[2];
    const float* Wph = (const float*)d_in[3];
    const float* bh  = (const float*)d_in[4];
    const float* bp  = (const float*)d_in[5];
    float* out = (float*)d_out;

    cudaFuncSetAttribute(VanillaRNN_54984171323420_kernel,
                         cudaFuncAttributeMaxDynamicSharedMemorySize, SM_TOTAL);
    VanillaRNN_54984171323420_kernel<<<NBLK, NTHR, SM_TOTAL>>>(
        x, Whx, Whh, Wph, bh, bp, out);
}

// round 6
// speedup vs baseline: 1.0555x; 1.0555x over previous
#include <cuda_runtime.h>
#include <cuda_fp16.h>
#include <cstdint>

// VanillaRNN via warp-level HMMA, fp16 3-pass hi/lo split.
// R6: 8 warps x 32 M-rows. All A_hi fragments register-resident (128 regs).
// Correction passes (W_lo.h_hi + W_hi.h_lo) accumulate in ONE f16 chain,
// operands pre-scaled by 2^8 to stay f16-normal; epilogue rescales by 2^-8.

#define BATCH 2048
#define SEQT  512
#define HDIM  256
#define NCOL  16
#define NBLK  128
#define NTHR  256
#define NSTEPS 510
#define SCALE   256.0f
#define INVSCALE 0.00390625f

// smem byte offsets
#define SM_W   0          // init: W_hi staging; steady: W_lo*2^8 [256 rows][512B]
#define SM_B   131072     // h buffers: [buf0 hi 8K | lo 8K][buf1 hi 8K | lo 8K]
#define SM_XR  163840     // x ring: 2 slots x 16 f32
#define SM_TOTAL 163968

__device__ __forceinline__ uint32_t s2u(const void* p) {
    uint32_t a;
    asm("{ .reg .u64 t; cvta.to.shared.u64 t, %1; cvt.u32.u64 %0, t; }" : "=r"(a) : "l"(p));
    return a;
}

#define LDSM4(r, a)                                                               \
    asm volatile("ldmatrix.sync.aligned.m8n8.x4.shared.b16 {%0,%1,%2,%3}, [%4];"  \
                 : "=r"((r)[0]), "=r"((r)[1]), "=r"((r)[2]), "=r"((r)[3])         \
                 : "r"(a))

__device__ __forceinline__ void mma_f32(float* d, const uint32_t* a,
                                        uint32_t b0, uint32_t b1) {
    asm volatile("mma.sync.aligned.m16n8k16.row.col.f32.f16.f16.f32 "
                 "{%0,%1,%2,%3}, {%4,%5,%6,%7}, {%8,%9}, {%0,%1,%2,%3};"
                 : "+f"(d[0]), "+f"(d[1]), "+f"(d[2]), "+f"(d[3])
                 : "r"(a[0]), "r"(a[1]), "r"(a[2]), "r"(a[3]), "r"(b0), "r"(b1));
}
__device__ __forceinline__ void mma_f16(uint32_t* d, const uint32_t* a,
                                        uint32_t b0, uint32_t b1) {
    asm volatile("mma.sync.aligned.m16n8k16.row.col.f16.f16.f16.f16 "
                 "{%0,%1}, {%2,%3,%4,%5}, {%6,%7}, {%0,%1};"
                 : "+r"(d[0]), "+r"(d[1])
                 : "r"(a[0]), "r"(a[1]), "r"(a[2]), "r"(a[3]), "r"(b0), "r"(b1));
}

__device__ __forceinline__ float tanh_fast(float v) {
    float e = __expf(2.0f * v);
    return 1.0f - __fdividef(2.0f, e + 1.0f);
}

__global__ void __launch_bounds__(NTHR, 1) VanillaRNN_54984171323420_kernel(
    const float* __restrict__ x,    // [2048, 512]
    const float* __restrict__ Whx,  // [256, 1]
    const float* __restrict__ Whh,  // [256, 256]
    const float* __restrict__ Wph,  // [10, 256]
    const float* __restrict__ bh,   // [256, 2048]
    const float* __restrict__ bp,   // [10, 2048]
    float* __restrict__ out)        // [2048, 10]
{
    extern __shared__ char smc[];
    const uint32_t sb = s2u(smc);
    const int tid = threadIdx.x;
    const int w = tid >> 5;          // warp 0..7 -> m rows [32w, 32w+32)
    const int l = tid & 31;
    const int lq = l >> 2;
    const int lr = (l & 3) * 2;
    const int lx = l >> 4;
    const int l7 = l & 7;
    const int m0 = 32 * w;
    const int j0 = blockIdx.x * NCOL;

    // ---------------- stage W_hi into smem (swizzled 512B rows) ----------------
    for (int idx = tid; idx < HDIM * HDIM; idx += NTHR) {
        int m = idx >> 8, k = idx & 255;
        __half hi = __float2half_rn(Whh[idx]);
        uint32_t ch = (uint32_t)(((k >> 3) ^ (m & 7)) << 4);
        *(__half*)(smc + SM_W + m * 512 + ch + (k & 7) * 2) = hi;
    }
    float xn1 = 0.0f;
    if (tid < NCOL) {
        const float* xr = x + (j0 + tid) * SEQT;
        *(float*)(smc + SM_XR + 64 + tid * 4) = xr[0];
        xn1 = xr[1];
    }
    __syncthreads();

    // ---------------- A_hi fragments -> registers (loop-invariant, 128 regs) ----
    const uint32_t rowAL0 = sb + SM_W + (uint32_t)(m0 + (l & 15)) * 512;
    const uint32_t rowAL1 = rowAL0 + 16 * 512;
    uint32_t ahi0[16][4], ahi1[16][4];
#pragma unroll
    for (int ks = 0; ks < 16; ks++) {
        const uint32_t ch = (uint32_t)(((2 * ks + lx) ^ l7) << 4);
        LDSM4(ahi0[ks], rowAL0 + ch);
        LDSM4(ahi1[ks], rowAL1 + ch);
    }
    __syncthreads();

    // ---------------- overwrite staging with W_lo * 2^8 ----------------
    for (int idx = tid; idx < HDIM * HDIM; idx += NTHR) {
        int m = idx >> 8, k = idx & 255;
        float wv = Whh[idx];
        __half hi = __float2half_rn(wv);
        __half lo = __float2half_rn((wv - __half2float(hi)) * SCALE);
        uint32_t ch = (uint32_t)(((k >> 3) ^ (m & 7)) << 4);
        *(__half*)(smc + SM_W + m * 512 + ch + (k & 7) * 2) = lo;
    }

    // ---------------- bias / Whx fragments (16 D elems per thread) ----------------
    float bias[16];
    float wx[2][2];
#pragma unroll
    for (int tm = 0; tm < 2; tm++) {
        wx[tm][0] = Whx[m0 + 16 * tm + lq];
        wx[tm][1] = Whx[m0 + 16 * tm + lq + 8];
#pragma unroll
        for (int tn = 0; tn < 2; tn++)
#pragma unroll
            for (int e = 0; e < 4; e++) {
                int m = m0 + 16 * tm + lq + ((e >> 1) ? 8 : 0);
                int n = 8 * tn + lr + (e & 1);
                bias[tm * 8 + tn * 4 + e] = bh[m * BATCH + j0 + n];
            }
    }

    // ---------------- prologue: h1 = tanh(b_h + Whx*x_0) -> buf0 ----------------
#pragma unroll
    for (int tm = 0; tm < 2; tm++)
#pragma unroll
        for (int tn = 0; tn < 2; tn++)
#pragma unroll
            for (int e = 0; e < 4; e++) {
                int n = 8 * tn + lr + (e & 1);
                int mh = e >> 1;
                int m = m0 + 16 * tm + lq + (mh ? 8 : 0);
                float xv = *(const float*)(smc + SM_XR + 64 + n * 4);
                float h = tanh_fast(bias[tm * 8 + tn * 4 + e] + wx[tm][mh] * xv);
                __half hi = __float2half_rn(h);
                __half lo = __float2half_rn((h - __half2float(hi)) * SCALE);
                uint32_t off = (uint32_t)n * 512 + ((((uint32_t)m >> 3) ^ (n & 7)) << 4) + (m & 7) * 2;
                *(__half*)(smc + SM_B + off) = hi;
                *(__half*)(smc + SM_B + 8192 + off) = lo;
            }
    if (tid < NCOL) *(float*)(smc + SM_XR + tid * 4) = xn1;  // slot0 <- x_1
    __syncthreads();

    const uint32_t rowBb = sb + SM_B + (uint32_t)(l & 15) * 512;

    // ================= recurrence: 510 HMMA steps, 1 bar/step =================
#pragma unroll 2
    for (int it = 0; it < NSTEPS; it++) {
        const int p = it & 1;                 // read buf p, write buf 1-p
        float xnext = 0.0f;
        if (tid < NCOL) xnext = x[(j0 + tid) * SEQT + it + 2];

        const uint32_t rowB = rowBb + (uint32_t)p * 16384;

        float d32[16];
#pragma unroll
        for (int q = 0; q < 16; q++) d32[q] = bias[q];
        uint32_t dlo[4][2];                   // f16x2 accum: [tm*2+tn][reg]
#pragma unroll
        for (int q = 0; q < 4; q++) { dlo[q][0] = 0u; dlo[q][1] = 0u; }

#pragma unroll
        for (int ks = 0; ks < 16; ks++) {
            const uint32_t ch = (uint32_t)(((2 * ks + lx) ^ l7) << 4);
            uint32_t bh4[4], bl4[4], al0[4], al1[4];
            LDSM4(bh4, rowB + ch);
            LDSM4(bl4, rowB + 8192 + ch);
            LDSM4(al0, rowAL0 + ch);
            LDSM4(al1, rowAL1 + ch);
            // main pass: W_hi . h_hi  (f32 accum)
            mma_f32(&d32[0],  ahi0[ks], bh4[0], bh4[2]);
            mma_f32(&d32[4],  ahi0[ks], bh4[1], bh4[3]);
            mma_f32(&d32[8],  ahi1[ks], bh4[0], bh4[2]);
            mma_f32(&d32[12], ahi1[ks], bh4[1], bh4[3]);
            // correction passes (x 2^8): W_lo.h_hi + W_hi.h_lo  (f16 accum)
            mma_f16(dlo[0], al0,      bh4[0], bh4[2]);
            mma_f16(dlo[0], ahi0[ks], bl4[0], bl4[2]);
            mma_f16(dlo[1], al0,      bh4[1], bh4[3]);
            mma_f16(dlo[1], ahi0[ks], bl4[1], bl4[3]);
            mma_f16(dlo[2], al1,      bh4[0], bh4[2]);
            mma_f16(dlo[2], ahi1[ks], bl4[0], bl4[2]);
            mma_f16(dlo[3], al1,      bh4[1], bh4[3]);
            mma_f16(dlo[3], ahi1[ks], bl4[1], bl4[3]);
        }

        // ---- epilogue: h = tanh(d32 + dlo*2^-8 + Whx*x) -> buf 1-p ----
        const uint32_t xsl = (uint32_t)(SM_XR + p * 64);
        const uint32_t bufw = (uint32_t)(SM_B + (1 - p) * 16384);
#pragma unroll
        for (int tm = 0; tm < 2; tm++)
#pragma unroll
            for (int tn = 0; tn < 2; tn++) {
                float2 lo01 = __half22float2(*(__half2*)&dlo[tm * 2 + tn][0]);
                float2 lo23 = __half22float2(*(__half2*)&dlo[tm * 2 + tn][1]);
                float lov[4] = {lo01.x, lo01.y, lo23.x, lo23.y};
#pragma unroll
                for (int e = 0; e < 4; e++) {
                    int idx = tm * 8 + tn * 4 + e;
                    int n = 8 * tn + lr + (e & 1);
                    int mh = e >> 1;
                    int m = m0 + 16 * tm + lq + (mh ? 8 : 0);
                    float xv = *(const float*)(smc + xsl + n * 4);
                    float pre = fmaf(wx[tm][mh], xv, fmaf(lov[e], INVSCALE, d32[idx]));
                    float h = tanh_fast(pre);
                    __half hi = __float2half_rn(h);
                    __half lo = __float2half_rn((h - __half2float(hi)) * SCALE);
                    uint32_t off = (uint32_t)n * 512 + ((((uint32_t)m >> 3) ^ (n & 7)) << 4) + (m & 7) * 2;
                    *(__half*)(smc + bufw + off) = hi;
                    *(__half*)(smc + bufw + 8192 + off) = lo;
                }
            }
        if (tid < NCOL) *(float*)(smc + SM_XR + (1 - p) * 64 + tid * 4) = xnext;
        __syncthreads();
    }

    // ================= projection: out = Wph @ h + bp =================
    // final h lives in buf0 (it=509 wrote buf 1-p = 0)
    if (tid < 10 * NCOL) {
        const int c = tid >> 4, j = tid & 15;
        float s = bp[c * BATCH + j0 + j];
        const float* wr = Wph + c * HDIM;
#pragma unroll 8
        for (int k = 0; k < HDIM; k++) {
            uint32_t off = (uint32_t)j * 512 + ((((uint32_t)k >> 3) ^ (j & 7)) << 4) + (k & 7) * 2;
            float hv = __half2float(*(__half*)(smc + SM_B + off)) +
                       __half2float(*(__half*)(smc + SM_B + 8192 + off)) * INVSCALE;
            s = fmaf(wr[k], hv, s);
        }
        out[(j0 + j) * 10 + c] = s;
    }
}

extern "C" void kernel_launch(void* const* d_in, const int* in_sizes, int n_in,
                              void* d_out, int out_size) {
    const float* x   = (const float*)d_in[0];
    const float* Whx = (const float*)d_in[1];
    const float* Whh = (const float*)d_in[2];
    const float* Wph = (const float*)d_in[3];
    const float* bh  = (const float*)d_in[4];
    const float* bp  = (const float*)d_in[5];
    float* out = (float*)d_out;

    cudaFuncSetAttribute(VanillaRNN_54984171323420_kernel,
                         cudaFuncAttributeMaxDynamicSharedMemorySize, SM_TOTAL);
    VanillaRNN_54984171323420_kernel<<<NBLK, NTHR, SM_TOTAL>>>(
        x, Whx, Whh, Wph, bh, bp, out);
}